// round 1
// baseline (speedup 1.0000x reference)
#include <cuda_runtime.h>
#include <climits>

#define NB 32
#define H 512
#define W 512
#define C 3
#define OUT 400
#define THRESH 0.7f

// Scratch (allocation-free): per-batch bbox + per-axis coord tables.
__device__ int   g_bounds[NB][4];      // rmin, rmax, cmin, cmax
__device__ int   g_i0[2][NB][OUT];     // axis 0 = rows, axis 1 = cols
__device__ int   g_i1[2][NB][OUT];
__device__ float g_wt[2][NB][OUT];

__global__ void init_bounds_kernel() {
    int b = threadIdx.x;
    if (b < NB) {
        g_bounds[b][0] = INT_MAX;
        g_bounds[b][1] = -1;
        g_bounds[b][2] = INT_MAX;
        g_bounds[b][3] = -1;
    }
}

#define BPB 8                       // blocks per batch
#define ROWS_PER_BLK (H / BPB)      // 64
#define TB 256

__global__ void bounds_kernel(const float* __restrict__ tensor) {
    int blk  = blockIdx.x;
    int b    = blk / BPB;
    int rb   = blk % BPB;
    int row0 = rb * ROWS_PER_BLK;

    const float4* base =
        (const float4*)(tensor + ((size_t)b * H + row0) * W);

    int rmin = INT_MAX, rmax = -1, cmin = INT_MAX, cmax = -1;

    const int NV = ROWS_PER_BLK * (W / 4);  // 64 * 128 = 8192 float4s
    for (int j = threadIdx.x; j < NV; j += TB) {
        float4 v = base[j];
        int r = j >> 7;            // j / 128
        int c = (j & 127) << 2;    // (j % 128) * 4
        bool any = false;
        if (v.x > THRESH) { any = true; cmin = min(cmin, c    ); cmax = max(cmax, c    ); }
        if (v.y > THRESH) { any = true; cmin = min(cmin, c + 1); cmax = max(cmax, c + 1); }
        if (v.z > THRESH) { any = true; cmin = min(cmin, c + 2); cmax = max(cmax, c + 2); }
        if (v.w > THRESH) { any = true; cmin = min(cmin, c + 3); cmax = max(cmax, c + 3); }
        if (any) {
            int rr = row0 + r;
            rmin = min(rmin, rr);
            rmax = max(rmax, rr);
        }
    }

    // warp reduce
    #pragma unroll
    for (int o = 16; o > 0; o >>= 1) {
        rmin = min(rmin, __shfl_xor_sync(0xFFFFFFFFu, rmin, o));
        rmax = max(rmax, __shfl_xor_sync(0xFFFFFFFFu, rmax, o));
        cmin = min(cmin, __shfl_xor_sync(0xFFFFFFFFu, cmin, o));
        cmax = max(cmax, __shfl_xor_sync(0xFFFFFFFFu, cmax, o));
    }

    __shared__ int s[4][TB / 32];
    int wid = threadIdx.x >> 5, lid = threadIdx.x & 31;
    if (lid == 0) { s[0][wid] = rmin; s[1][wid] = rmax; s[2][wid] = cmin; s[3][wid] = cmax; }
    __syncthreads();
    if (threadIdx.x == 0) {
        #pragma unroll
        for (int i = 1; i < TB / 32; i++) {
            rmin = min(rmin, s[0][i]); rmax = max(rmax, s[1][i]);
            cmin = min(cmin, s[2][i]); cmax = max(cmax, s[3][i]);
        }
        atomicMin(&g_bounds[b][0], rmin);
        atomicMax(&g_bounds[b][1], rmax);
        atomicMin(&g_bounds[b][2], cmin);
        atomicMax(&g_bounds[b][3], cmax);
    }
}

// Exact replica of _axis_coords (float32 op order preserved).
__global__ void coords_kernel() {
    int b = blockIdx.x;
    for (int t = threadIdx.x; t < 2 * OUT; t += blockDim.x) {
        int axis = t / OUT;   // 0 = rows (left/right), 1 = cols (top/bot)
        int i    = t % OUT;
        int lo = g_bounds[b][axis * 2 + 0];
        int hi = g_bounds[b][axis * 2 + 1];
        if (hi < lo) {        // empty mask: jnp.argmax on all-False -> (0, n-1)
            lo = 0;
            hi = H - 1;       // H == W == 512
        }
        float size = (float)(hi - lo);
        float src  = ((float)i + 0.5f) * size / (float)OUT - 0.5f;
        float mx   = fmaxf(size - 1.0f, 0.0f);
        src = fminf(fmaxf(src, 0.0f), mx);
        int   i0 = (int)floorf(src);
        int   i1 = min(i0 + 1, max(hi - lo - 1, 0));
        float w  = src - (float)i0;
        g_i0[axis][b][i] = lo + i0;
        g_i1[axis][b][i] = lo + i1;
        g_wt[axis][b][i] = w;
    }
}

__global__ void resize_kernel(const float* __restrict__ img,
                              float* __restrict__ out) {
    int idx = blockIdx.x * blockDim.x + threadIdx.x;
    const int total = NB * OUT * OUT;
    if (idx >= total) return;

    int c = idx % OUT;
    int t = idx / OUT;
    int r = t % OUT;
    int b = t / OUT;

    int   r0 = g_i0[0][b][r];
    int   r1 = g_i1[0][b][r];
    float wr = g_wt[0][b][r];
    int   c0 = g_i0[1][b][c];
    int   c1 = g_i1[1][b][c];
    float wc = g_wt[1][b][c];

    const float* base = img + (size_t)b * H * W * C;
    const float* p00 = base + ((size_t)r0 * W + c0) * C;
    const float* p01 = base + ((size_t)r0 * W + c1) * C;
    const float* p10 = base + ((size_t)r1 * W + c0) * C;
    const float* p11 = base + ((size_t)r1 * W + c1) * C;

    float omwc = 1.0f - wc;
    float omwr = 1.0f - wr;

    float* o = out + (size_t)idx * C;
    #pragma unroll
    for (int ch = 0; ch < C; ch++) {
        float a00 = __ldg(p00 + ch);
        float a01 = __ldg(p01 + ch);
        float a10 = __ldg(p10 + ch);
        float a11 = __ldg(p11 + ch);
        float topv = a00 * omwc + a01 * wc;
        float botv = a10 * omwc + a11 * wc;
        o[ch] = topv * omwr + botv * wr;
    }
}

extern "C" void kernel_launch(void* const* d_in, const int* in_sizes, int n_in,
                              void* d_out, int out_size) {
    // Robust input-order detection: image has 25,165,824 elems, tensor 8,388,608.
    const float* image  = (const float*)d_in[0];
    const float* tensor = (const float*)d_in[1];
    if (n_in >= 2 && in_sizes[0] < in_sizes[1]) {
        image  = (const float*)d_in[1];
        tensor = (const float*)d_in[0];
    }
    float* out = (float*)d_out;

    init_bounds_kernel<<<1, 32>>>();
    bounds_kernel<<<NB * BPB, TB>>>(tensor);
    coords_kernel<<<NB, 256>>>();

    const int total = NB * OUT * OUT;
    resize_kernel<<<(total + 255) / 256, 256>>>(image, out);
}

// round 2
// speedup vs baseline: 1.1582x; 1.1582x over previous
#include <cuda_runtime.h>
#include <climits>

#define NB 32
#define H 512
#define W 512
#define C 3
#define OUT 400
#define THRESH 0.7f

// Scratch (allocation-free): per-batch bbox. rmin, rmax, cmin, cmax.
__device__ int g_bounds[NB][4];

__global__ void init_bounds_kernel() {
    int b = threadIdx.x;
    if (b < NB) {
        g_bounds[b][0] = INT_MAX;
        g_bounds[b][1] = -1;
        g_bounds[b][2] = INT_MAX;
        g_bounds[b][3] = -1;
    }
}

#define BPB 16                      // blocks per batch
#define ROWS_PER_BLK (H / BPB)      // 32
#define TB 256

__global__ void bounds_kernel(const float* __restrict__ tensor) {
    int blk  = blockIdx.x;
    int b    = blk / BPB;
    int rb   = blk % BPB;
    int row0 = rb * ROWS_PER_BLK;

    const float4* base =
        (const float4*)(tensor + ((size_t)b * H + row0) * W);

    int rmin = INT_MAX, rmax = -1, cmin = INT_MAX, cmax = -1;

    const int NV = ROWS_PER_BLK * (W / 4);  // 32 * 128 = 4096 float4s
    for (int j = threadIdx.x; j < NV; j += TB) {
        float4 v = base[j];
        int r = j >> 7;            // j / 128
        int c = (j & 127) << 2;    // (j % 128) * 4
        bool any = false;
        if (v.x > THRESH) { any = true; cmin = min(cmin, c    ); cmax = max(cmax, c    ); }
        if (v.y > THRESH) { any = true; cmin = min(cmin, c + 1); cmax = max(cmax, c + 1); }
        if (v.z > THRESH) { any = true; cmin = min(cmin, c + 2); cmax = max(cmax, c + 2); }
        if (v.w > THRESH) { any = true; cmin = min(cmin, c + 3); cmax = max(cmax, c + 3); }
        if (any) {
            int rr = row0 + r;
            rmin = min(rmin, rr);
            rmax = max(rmax, rr);
        }
    }

    #pragma unroll
    for (int o = 16; o > 0; o >>= 1) {
        rmin = min(rmin, __shfl_xor_sync(0xFFFFFFFFu, rmin, o));
        rmax = max(rmax, __shfl_xor_sync(0xFFFFFFFFu, rmax, o));
        cmin = min(cmin, __shfl_xor_sync(0xFFFFFFFFu, cmin, o));
        cmax = max(cmax, __shfl_xor_sync(0xFFFFFFFFu, cmax, o));
    }

    __shared__ int s[4][TB / 32];
    int wid = threadIdx.x >> 5, lid = threadIdx.x & 31;
    if (lid == 0) { s[0][wid] = rmin; s[1][wid] = rmax; s[2][wid] = cmin; s[3][wid] = cmax; }
    __syncthreads();
    if (threadIdx.x == 0) {
        #pragma unroll
        for (int i = 1; i < TB / 32; i++) {
            rmin = min(rmin, s[0][i]); rmax = max(rmax, s[1][i]);
            cmin = min(cmin, s[2][i]); cmax = max(cmax, s[3][i]);
        }
        atomicMin(&g_bounds[b][0], rmin);
        atomicMax(&g_bounds[b][1], rmax);
        atomicMin(&g_bounds[b][2], cmin);
        atomicMax(&g_bounds[b][3], cmax);
    }
}

// Inline replica of _axis_coords (float32 op order preserved).
// Handles the all-False-mask case: jnp.argmax on all-False gives (0, n-1).
__device__ __forceinline__ void axis_coords(int lo, int hi, int i,
                                            int& i0g, int& i1g, float& w) {
    if (hi < lo) { lo = 0; hi = H - 1; }   // H == W == 512
    float size = (float)(hi - lo);
    float src  = ((float)i + 0.5f) * size / (float)OUT - 0.5f;
    float mx   = fmaxf(size - 1.0f, 0.0f);
    src = fminf(fmaxf(src, 0.0f), mx);
    int   i0 = (int)floorf(src);
    int   i1 = min(i0 + 1, max(hi - lo - 1, 0));
    w = src - (float)i0;
    i0g = lo + i0;
    i1g = lo + i1;
}

#define RT 128   // threads per resize block

// One block per (batch, output row). Stage input rows r0, r1 into smem with
// coalesced float4 loads; bilinear gather served from shared memory.
__global__ __launch_bounds__(RT) void resize_kernel(const float* __restrict__ img,
                                                    float* __restrict__ out) {
    int blk = blockIdx.x;          // b * OUT + r
    int b   = blk / OUT;
    int r   = blk - b * OUT;

    __shared__ float row0[W * C];  // 6 KB
    __shared__ float row1[W * C];  // 6 KB

    int rlo = g_bounds[b][0], rhi = g_bounds[b][1];
    int clo = g_bounds[b][2], chi = g_bounds[b][3];

    int r0, r1; float wr;
    axis_coords(rlo, rhi, r, r0, r1, wr);

    const float4* s0 = (const float4*)(img + ((size_t)b * H + r0) * W * C);
    const float4* s1 = (const float4*)(img + ((size_t)b * H + r1) * W * C);
    float4* d0 = (float4*)row0;
    float4* d1 = (float4*)row1;
    #pragma unroll
    for (int it = 0; it < (W * C / 4) / RT; it++) {   // 384/128 = 3 exact
        int j = it * RT + threadIdx.x;
        d0[j] = s0[j];
        d1[j] = s1[j];
    }
    __syncthreads();

    float omwr = 1.0f - wr;
    float* orow = out + (size_t)blk * OUT * C;

    for (int c = threadIdx.x; c < OUT; c += RT) {
        int c0, c1; float wc;
        axis_coords(clo, chi, c, c0, c1, wc);
        float omwc = 1.0f - wc;

        int o00 = c0 * C, o01 = c1 * C;
        float* o = orow + c * C;
        #pragma unroll
        for (int ch = 0; ch < C; ch++) {
            float a00 = row0[o00 + ch];
            float a01 = row0[o01 + ch];
            float a10 = row1[o00 + ch];
            float a11 = row1[o01 + ch];
            float topv = a00 * omwc + a01 * wc;
            float botv = a10 * omwc + a11 * wc;
            o[ch] = topv * omwr + botv * wr;
        }
    }
}

extern "C" void kernel_launch(void* const* d_in, const int* in_sizes, int n_in,
                              void* d_out, int out_size) {
    // Input-order detection: image has 25,165,824 elems, tensor 8,388,608.
    const float* image  = (const float*)d_in[0];
    const float* tensor = (const float*)d_in[1];
    if (n_in >= 2 && in_sizes[0] < in_sizes[1]) {
        image  = (const float*)d_in[1];
        tensor = (const float*)d_in[0];
    }
    float* out = (float*)d_out;

    init_bounds_kernel<<<1, 32>>>();
    bounds_kernel<<<NB * BPB, TB>>>(tensor);
    resize_kernel<<<NB * OUT, RT>>>(image, out);
}